// round 11
// baseline (speedup 1.0000x reference)
#include <cuda_runtime.h>
#include <cuda_fp16.h>
#include <cstdint>

#define NB 4096
#define NC 64
#define DD 32
#define KK 1024   // H1*H2
#define NSTAGE 4

// ---------------------------------------------------------------- W fragments
// K matrix pre-converted to fp16, laid out per mma.m16n8k16 A-fragment:
// g_Wf16[ch(64)][mt(4)][lane(32)] = uint4 {a0,a1,a2,a3} (each fp16x2).
// a0=(r, k0|k0+1) a1=(r+8, ..) a2=(r, k0+8|k0+9) a3=(r+8, ..),
// r = 16*mt + lane/4, k0 = 2*(lane%4); global k = 16*ch + klocal.
__device__ __align__(16) uint4 g_Wf16[64 * 4 * 32];

__global__ void wfrag_kernel(const float* __restrict__ K) {
    int idx = blockIdx.x * blockDim.x + threadIdx.x;  // 8192
    int lane = idx & 31, mt = (idx >> 5) & 3, ch = idx >> 7;
    int r0 = 16 * mt + (lane >> 2);
    int k0 = 16 * ch + 2 * (lane & 3);
    uint32_t q[4];
#pragma unroll
    for (int u = 0; u < 4; u++) {
        int r = r0 + (u & 1) * 8;
        int k = k0 + (u >> 1) * 8;
        __half2 h = __floats2half2_rn(K[r * KK + k], K[r * KK + k + 1]);
        q[u] = *(uint32_t*)&h;
    }
    g_Wf16[idx] = make_uint4(q[0], q[1], q[2], q[3]);
}

// ---------------------------------------------------------------- helpers
__device__ __forceinline__ uint32_t smem_u32(const void* p) {
    uint32_t a;
    asm("{ .reg .u64 t; cvta.to.shared.u64 t, %1; cvt.u32.u64 %0, t; }"
        : "=r"(a) : "l"(p));
    return a;
}
__device__ __forceinline__ uint32_t f16x2_of(float hi, float lo) {
    uint32_t r;
    asm("cvt.rn.f16x2.f32 %0, %1, %2;" : "=r"(r) : "f"(hi), "f"(lo));
    return r;
}
__device__ __forceinline__ uint32_t hmul2(uint32_t a, uint32_t b) {
    uint32_t r;
    asm("mul.f16x2 %0, %1, %2;" : "=r"(r) : "r"(a), "r"(b));
    return r;
}
__device__ __forceinline__ void mma_f16(float& c0, float& c1, float& c2, float& c3,
                                        uint32_t a0, uint32_t a1, uint32_t a2,
                                        uint32_t a3, uint32_t b0, uint32_t b1) {
    asm volatile(
        "mma.sync.aligned.m16n8k16.row.col.f32.f16.f16.f32 "
        "{%0,%1,%2,%3}, {%4,%5,%6,%7}, {%8,%9}, {%0,%1,%2,%3};"
        : "+f"(c0), "+f"(c1), "+f"(c2), "+f"(c3)
        : "r"(a0), "r"(a1), "r"(a2), "r"(a3), "r"(b0), "r"(b1));
}
#define CP_ASYNC16(dst, src) \
    asm volatile("cp.async.cg.shared.global [%0], [%1], 16;" \
                 :: "r"(dst), "l"(src) : "memory")
#define CP_COMMIT() asm volatile("cp.async.commit_group;" ::: "memory")
#define CP_WAIT(n)  asm volatile("cp.async.wait_group %0;" :: "n"(n) : "memory")

// ---------------------------------------------------------------- main kernel
// CTA: 256 threads = 8 warps = 4 batches; 2 warps per batch (m-split):
// warp (w&1) covers m-tiles {2*(w&1), 2*(w&1)+1} for all 32 d-columns.
// Per-batch GEMM: OUT[c(64), d(32)] = W[c,k] * Z[k,d], K=1024, fp16 1-pass.
// W streamed once per CTA through a shared 4-stage ring (2 KB per stage =
// one full chunk, all 4 m-tiles). Threads t<128 produce (one cp.async.cg
// each per chunk); all warps consume their m-half via conflict-free LDS.
// Classic multistage ordering: wait_group(NSTAGE-2) -> syncthreads ->
// consume + issue stage ch+NSTAGE-1.
__global__ __launch_bounds__(256, 3)
void cin_mma_kernel(const float* __restrict__ X, const float* __restrict__ Y,
                    float* __restrict__ out_mat, float* __restrict__ out_fin) {
    __shared__ float x_s[4 * KK];                  // 16 KB
    __shared__ uint4 w_ring[NSTAGE][4][32];        // 8 KB

    const int t = threadIdx.x;
    const int lane = t & 31;
    const int w = t >> 5;
    const int bl = w >> 1;            // local batch 0..3
    const int mh = w & 1;             // m-half: m-tiles {2*mh, 2*mh+1}
    const int b = blockIdx.x * 4 + bl;
    const int g = lane >> 2;          // row group / d offset
    const int jm = lane & 3;

    // producer role: threads 0..127 copy element (pm, plane) of each chunk
    const bool producer = (t < 128);
    const int pm = (t >> 5) & 3;      // mtile this producer covers
    const int plane = lane;
    const uint32_t wdst0 = smem_u32(&w_ring[0][pm][plane]);
    const uint4* wsrc = g_Wf16 + pm * 32 + plane;  // + ch*128

    // stage x (coalesced float4)
    {
        const float4* xg = (const float4*)(X + (size_t)blockIdx.x * 4 * KK);
        float4* xs4 = (float4*)x_s;
#pragma unroll
        for (int rep = 0; rep < 4; rep++) xs4[rep * 256 + t] = xg[rep * 256 + t];
    }

    // prologue: fill stages 0..NSTAGE-2
#pragma unroll
    for (int s = 0; s < NSTAGE - 1; s++) {
        if (producer) CP_ASYNC16(wdst0 + s * 2048, wsrc + s * 128);
        CP_COMMIT();
    }
    __syncthreads();   // also covers x_s

    // y pre-packed f16x2. B frag (n8k16 col): b0 <- klocal {2jm, 2jm+1},
    // b1 <- {2jm+8, 2jm+9}; j = p*16 + klocal; d = g + 8*nf.
    const float* yb = Y + (size_t)b * KK;
    uint32_t y2[4][4];
#pragma unroll
    for (int nf = 0; nf < 4; nf++) {
        int d = g + 8 * nf;
#pragma unroll
        for (int p = 0; p < 2; p++) {
            y2[nf][2 * p] = f16x2_of(yb[(16 * p + 2 * jm + 1) * 32 + d],
                                     yb[(16 * p + 2 * jm) * 32 + d]);
            y2[nf][2 * p + 1] = f16x2_of(yb[(16 * p + 8 + 2 * jm + 1) * 32 + d],
                                         yb[(16 * p + 8 + 2 * jm) * 32 + d]);
        }
    }

    float acc[2][4][4];
#pragma unroll
    for (int m = 0; m < 2; m++)
#pragma unroll
        for (int n = 0; n < 4; n++)
#pragma unroll
            for (int q = 0; q < 4; q++) acc[m][n][q] = 0.0f;

    const float* xrow = x_s + bl * KK;

#pragma unroll 2
    for (int ch = 0; ch < 64; ch++) {
        const int st = ch & (NSTAGE - 1);
        const int i = ch >> 1;
        const int p = ch & 1;

        CP_WAIT(NSTAGE - 2);          // stage ch resident (producers; nop else)
        __syncthreads();              // visible to all warps

        // this warp's A fragments for chunk ch
        uint4 a0 = w_ring[st][2 * mh][lane];
        uint4 a1 = w_ring[st][2 * mh + 1][lane];

        // B fragments: bf[nf][r] = f16(xi) * y2[nf][2p+r]   (HMUL2)
        uint32_t bf[4][2];
#pragma unroll
        for (int nf = 0; nf < 4; nf++) {
            const float xi = xrow[i * 32 + g + 8 * nf];
            const uint32_t xi2 = f16x2_of(xi, xi);
            bf[nf][0] = hmul2(xi2, y2[nf][2 * p]);
            bf[nf][1] = hmul2(xi2, y2[nf][2 * p + 1]);
        }

#pragma unroll
        for (int nf = 0; nf < 4; nf++) {
            mma_f16(acc[0][nf][0], acc[0][nf][1], acc[0][nf][2], acc[0][nf][3],
                    a0.x, a0.y, a0.z, a0.w, bf[nf][0], bf[nf][1]);
            mma_f16(acc[1][nf][0], acc[1][nf][1], acc[1][nf][2], acc[1][nf][3],
                    a1.x, a1.y, a1.z, a1.w, bf[nf][0], bf[nf][1]);
        }

        // produce stage ch+NSTAGE-1 (safe: all threads passed this iter's sync)
        if (producer && ch + NSTAGE - 1 < 64)
            CP_ASYNC16(wdst0 + ((ch + NSTAGE - 1) & (NSTAGE - 1)) * 2048,
                       wsrc + (ch + NSTAGE - 1) * 128);
        CP_COMMIT();
    }

    // ----- epilogue: D frag rows c = 16*(2*mh+m) + g (+8),
    // cols d = 8*nf + 2*jm + {0,1}. Each warp owns distinct c rows.
    float* om = out_mat + (size_t)b * (NC * DD);
    float* fb = out_fin + (size_t)b * NC;
#pragma unroll
    for (int m = 0; m < 2; m++) {
        const int c0 = 16 * (2 * mh + m) + g;
        float s0 = 0.0f, s1 = 0.0f;
#pragma unroll
        for (int nf = 0; nf < 4; nf++) {
            int d0 = 8 * nf + 2 * jm;
            *(float2*)&om[c0 * DD + d0] =
                make_float2(acc[m][nf][0], acc[m][nf][1]);
            *(float2*)&om[(c0 + 8) * DD + d0] =
                make_float2(acc[m][nf][2], acc[m][nf][3]);
            s0 += acc[m][nf][0] + acc[m][nf][1];
            s1 += acc[m][nf][2] + acc[m][nf][3];
        }
        // sum across the quad (lanes sharing g): covers all 32 d
#pragma unroll
        for (int o = 1; o <= 2; o <<= 1) {
            s0 += __shfl_xor_sync(0xffffffffu, s0, o);
            s1 += __shfl_xor_sync(0xffffffffu, s1, o);
        }
        if (jm == 0) { fb[c0] = s0; fb[c0 + 8] = s1; }
    }
}

extern "C" void kernel_launch(void* const* d_in, const int* in_sizes, int n_in,
                              void* d_out, int out_size) {
    const float* X = (const float*)d_in[0];
    const float* Y = (const float*)d_in[1];
    const float* K = (const float*)d_in[2];
    float* om = (float*)d_out;
    float* fin = om + (size_t)NB * NC * DD;

    wfrag_kernel<<<32, 256>>>(K);
    cin_mma_kernel<<<NB / 4, 256>>>(X, Y, om, fin);
}